// round 15
// baseline (speedup 1.0000x reference)
#include <cuda_runtime.h>
#include <cuda_fp16.h>
#include <cstdint>

#define BB  32
#define DD  128
#define CLN 1024
#define QLN 512

// ---------------- scratch (device globals; no allocations allowed) ----------
__device__ __half g_Aeffh[BB * CLN * DD];          // wq + wqc*C^T (fp16)
__device__ float  g_bias[BB * CLN];
__device__ __half g_Sh[(size_t)BB * CLN * QLN];    // exp(S) fp16 (B, CL, QL)
__device__ float  g_rsum[BB * CLN];
__device__ float  g_csum[BB * QLN];
__device__ __half g_Tth[BB * DD * QLN];            // (S2^T C)^T fp16 (B, D, QL)
__device__ __half g_Qh[BB * DD * QLN];             // Q fp16
__device__ __half g_Ch[BB * DD * CLN];             // C fp16

// ---------------- helpers -----------------------------------------------------
__device__ __forceinline__ uint32_t s2u(const void* p) {
    uint32_t a;
    asm("{ .reg .u64 t; cvta.to.shared.u64 t, %1; cvt.u32.u64 %0, t; }" : "=r"(a) : "l"(p));
    return a;
}
#define CPC()  asm volatile("cp.async.commit_group;" ::: "memory")
#define CPW0() asm volatile("cp.async.wait_group 0;" ::: "memory")
#define CPW1() asm volatile("cp.async.wait_group 1;" ::: "memory")

// ---- K=16 rows (stride 24 halves = 48B), used by g1 --------------------------
__device__ __forceinline__ void cfillH(uint32_t sb, const __half* __restrict__ g,
                                       int ld, int row0, int k0, int t) {
    int r = t >> 1, q = t & 1;
    asm volatile("cp.async.cg.shared.global [%0], [%1], 16;"
                 :: "r"(sb + r * 48 + (q << 4)),
                    "l"(g + (size_t)(row0 + r) * ld + k0 + (q << 3)));
}
__device__ __forceinline__ void tloadH128(const __half* __restrict__ g, int ld,
                                          int n0, int k0, int t, __half v[8]) {
    int q = t & 127, cs = (t >> 7) << 3;
#pragma unroll
    for (int i = 0; i < 8; ++i)
        v[i] = g[(size_t)(k0 + cs + i) * ld + n0 + q];
}
__device__ __forceinline__ void tstoreH128(__half* __restrict__ smf, int t, const __half v[8]) {
    int q = t & 127, cs = (t >> 7) << 3;
#pragma unroll
    for (int j = 0; j < 4; ++j)
        *(__half2*)(smf + q * 24 + cs + 2 * j) = __halves2half2(v[2 * j], v[2 * j + 1]);
}

// ---- K=32 rows (stride 40 halves = 80B), used by g3/g24 ----------------------
__device__ __forceinline__ void cfill32_128(uint32_t sb, const __half* __restrict__ g,
                                            int ld, int row0, int k0, int t) {
#pragma unroll
    for (int j = 0; j < 2; ++j) {
        int lin = t + (j << 8);
        int r = lin >> 2, q = lin & 3;
        asm volatile("cp.async.cg.shared.global [%0], [%1], 16;"
                     :: "r"(sb + r * 80 + (q << 4)),
                        "l"(g + (size_t)(row0 + r) * ld + k0 + (q << 3)));
    }
}
__device__ __forceinline__ void cfill32_64(uint32_t sb, const __half* __restrict__ g,
                                           int ld, int row0, int k0, int t) {
    int r = t >> 2, q = t & 3;
    asm volatile("cp.async.cg.shared.global [%0], [%1], 16;"
                 :: "r"(sb + r * 80 + (q << 4)),
                    "l"(g + (size_t)(row0 + r) * ld + k0 + (q << 3)));
}
// transposed fill, 64-n x 32-k: each thread 8 k at fixed n  (g3 B)
__device__ __forceinline__ void tloadH64_32(const __half* __restrict__ g, int ld,
                                            int n0, int k0, int t, __half v[8]) {
    int q = t & 63, cs = (t >> 6) << 3;
#pragma unroll
    for (int i = 0; i < 8; ++i)
        v[i] = g[(size_t)(k0 + cs + i) * ld + n0 + q];
}
__device__ __forceinline__ void tstoreH64_32(__half* __restrict__ smf, int t, const __half v[8]) {
    int q = t & 63, cs = (t >> 6) << 3;
#pragma unroll
    for (int j = 0; j < 4; ++j)
        *(__half2*)(smf + q * 40 + cs + 2 * j) = __halves2half2(v[2 * j], v[2 * j + 1]);
}

// ---------------- mma.sync fp16 m16n8k16, fp32 accumulate ---------------------
#define MMA_F16(D, A, B)                                                           \
    asm volatile(                                                                  \
        "mma.sync.aligned.m16n8k16.row.col.f32.f16.f16.f32 "                       \
        "{%0,%1,%2,%3}, {%4,%5,%6,%7}, {%8,%9}, {%0,%1,%2,%3};"                    \
        : "+f"((D)[0]), "+f"((D)[1]), "+f"((D)[2]), "+f"((D)[3])                   \
        : "r"((A)[0]), "r"((A)[1]), "r"((A)[2]), "r"((A)[3]),                      \
          "r"((B)[0]), "r"((B)[1]))

// g1: warp tile 64x32 (4 mi x 4 ni), stride-24 smem, one k16
__device__ __forceinline__ void mma_chunkH44(const __half* __restrict__ As,
                                             const __half* __restrict__ Bs,
                                             float acc[4][4][4],
                                             int wm, int wn, int g, int tg) {
    int co = tg << 1;
    unsigned a[4][4], bf[4][2];
#pragma unroll
    for (int mi = 0; mi < 4; ++mi) {
        const __half* p = As + (wm + (mi << 4) + g) * 24 + co;
        a[mi][0] = *(const unsigned*)(p);
        a[mi][1] = *(const unsigned*)(p + 192);
        a[mi][2] = *(const unsigned*)(p + 8);
        a[mi][3] = *(const unsigned*)(p + 200);
    }
#pragma unroll
    for (int ni = 0; ni < 4; ++ni) {
        const __half* p = Bs + (wn + (ni << 3) + g) * 24 + co;
        bf[ni][0] = *(const unsigned*)(p);
        bf[ni][1] = *(const unsigned*)(p + 8);
    }
#pragma unroll
    for (int mi = 0; mi < 4; ++mi)
#pragma unroll
        for (int ni = 0; ni < 4; ++ni) MMA_F16(acc[mi][ni], a[mi], bf[ni]);
}

// g3: warp tile 64x16 (4 mi x 2 ni), stride-40 smem, K=32 (2 k16 steps)
__device__ __forceinline__ void mma_g3_k32(const __half* __restrict__ As,
                                           const __half* __restrict__ Bs,
                                           float acc[4][2][4],
                                           int wm, int wn, int g, int tg) {
#pragma unroll
    for (int k16 = 0; k16 < 2; ++k16) {
        int co = (k16 << 4) + (tg << 1);
        unsigned a[4][4], bf[2][2];
#pragma unroll
        for (int mi = 0; mi < 4; ++mi) {
            const __half* p = As + (wm + (mi << 4) + g) * 40 + co;
            a[mi][0] = *(const unsigned*)(p);
            a[mi][1] = *(const unsigned*)(p + 320);
            a[mi][2] = *(const unsigned*)(p + 8);
            a[mi][3] = *(const unsigned*)(p + 328);
        }
#pragma unroll
        for (int ni = 0; ni < 2; ++ni) {
            const __half* p = Bs + (wn + (ni << 3) + g) * 40 + co;
            bf[ni][0] = *(const unsigned*)(p);
            bf[ni][1] = *(const unsigned*)(p + 8);
        }
#pragma unroll
        for (int mi = 0; mi < 4; ++mi)
#pragma unroll
            for (int ni = 0; ni < 2; ++ni) MMA_F16(acc[mi][ni], a[mi], bf[ni]);
    }
}

// g24: warp tile 32x32 per B (2 mi x 4 ni), B1/B2 serialized (low regs), K=32
__device__ __forceinline__ void mma_g24_k32(const __half* __restrict__ As,
                                            const __half* __restrict__ Bs1,
                                            const __half* __restrict__ Bs2,
                                            float ac1[2][4][4], float ac2[2][4][4],
                                            int wm, int wn, int g, int tg) {
#pragma unroll
    for (int k16 = 0; k16 < 2; ++k16) {
        int co = (k16 << 4) + (tg << 1);
        unsigned a[2][4];
#pragma unroll
        for (int mi = 0; mi < 2; ++mi) {
            const __half* p = As + (wm + (mi << 4) + g) * 40 + co;
            a[mi][0] = *(const unsigned*)(p);
            a[mi][1] = *(const unsigned*)(p + 320);
            a[mi][2] = *(const unsigned*)(p + 8);
            a[mi][3] = *(const unsigned*)(p + 328);
        }
#pragma unroll
        for (int ni = 0; ni < 4; ++ni) {
            unsigned b[2];
            const __half* p = Bs1 + (wn + (ni << 3) + g) * 40 + co;
            b[0] = *(const unsigned*)(p);
            b[1] = *(const unsigned*)(p + 8);
            MMA_F16(ac1[0][ni], a[0], b);
            MMA_F16(ac1[1][ni], a[1], b);
        }
#pragma unroll
        for (int ni = 0; ni < 4; ++ni) {
            unsigned b[2];
            const __half* p = Bs2 + (wn + (ni << 3) + g) * 40 + co;
            b[0] = *(const unsigned*)(p);
            b[1] = *(const unsigned*)(p + 8);
            MMA_F16(ac2[0][ni], a[0], b);
            MMA_F16(ac2[1][ni], a[1], b);
        }
    }
}

// ---------------- prepC: Aeff/bias + fp16 copies of C and Q + zero sums -------
__global__ __launch_bounds__(256) void prepC_kernel(const float* __restrict__ C,
                                                    const float* __restrict__ Q,
                                                    const float* __restrict__ W) {
    __shared__ float tile[128 * 68];
    int b = blockIdx.y, c0 = blockIdx.x << 6, bx = blockIdx.x;
    int t = threadIdx.x, warp = t >> 5, lane = t & 31;
    int gi = (blockIdx.y * 16 + blockIdx.x) * 256 + t;
    if (gi < BB * CLN) g_rsum[gi] = 0.f;
    if (gi < BB * QLN) g_csum[gi] = 0.f;
#pragma unroll
    for (int i = 0; i < 8; ++i) {
        int idx = t + (i << 8);
        int d = idx >> 4, c4 = idx & 15;
        float4 v = *(const float4*)(C + ((size_t)b * DD + d) * CLN + c0 + (c4 << 2));
        *(float4*)(tile + d * 68 + (c4 << 2)) = v;
    }
    __syncthreads();
#pragma unroll
    for (int i = 0; i < 32; ++i) {
        int idx = i * 256 + t;
        int d = idx >> 6, cc = idx & 63;
        g_Ch[((size_t)b * DD + d) * CLN + c0 + cc] = __float2half(tile[d * 68 + cc]);
    }
    {
        const float* Qb = Q + (size_t)b * DD * QLN;
        __half* Qhb = g_Qh + (size_t)b * DD * QLN;
#pragma unroll
        for (int i = 0; i < 16; ++i) {
            int idx = bx * 4096 + i * 256 + t;
            Qhb[idx] = __float2half(Qb[idx]);
        }
    }
#pragma unroll
    for (int k = 0; k < 8; ++k) {
        int cc = (warp << 3) + k;
        size_t rc = (size_t)b * CLN + c0 + cc;
        const float* w = W + rc * (3 * DD);
        int d0 = lane << 2;
        float4 wq = *(const float4*)(w + d0);
        float4 wc = *(const float4*)(w + DD + d0);
        float4 wqc = *(const float4*)(w + 2 * DD + d0);
        float ct0 = tile[(d0 + 0) * 68 + cc];
        float ct1 = tile[(d0 + 1) * 68 + cc];
        float ct2 = tile[(d0 + 2) * 68 + cc];
        float ct3 = tile[(d0 + 3) * 68 + cc];
        *(__half2*)(g_Aeffh + (rc << 7) + d0) =
            __floats2half2_rn(wq.x + wqc.x * ct0, wq.y + wqc.y * ct1);
        *(__half2*)(g_Aeffh + (rc << 7) + d0 + 2) =
            __floats2half2_rn(wq.z + wqc.z * ct2, wq.w + wqc.w * ct3);
        float v = wc.x * ct0 + wc.y * ct1 + wc.z * ct2 + wc.w * ct3;
#pragma unroll
        for (int o = 16; o; o >>= 1) v += __shfl_xor_sync(0xffffffffu, v, o);
        if (lane == 0) g_bias[rc] = v;
    }
}

// ---------------- G1: expSh = exp(Aeff @ Q + bias); row/col sums via atomics --
__global__ __launch_bounds__(256) void g1_mma() {
    __shared__ __align__(16) __half smh[12288];
    int b = blockIdx.z, n0 = blockIdx.x << 7, m0 = blockIdx.y << 7;
    const __half* A = g_Aeffh + (size_t)b * CLN * DD;
    const __half* Qp = g_Qh + (size_t)b * DD * QLN;
    uint32_t su = s2u(smh);
    int t = threadIdx.x, lane = t & 31, warp = t >> 5;
    int g = lane >> 2, tg = lane & 3;
    int wm = (warp >> 2) << 6, wn = (warp & 3) << 5;
    float acc[4][4][4] = {};
    const int KT = 8;
    __half bv[8];
    cfillH(su, A, DD, m0, 0, t);
    tloadH128(Qp, QLN, n0, 0, t, bv);
    tstoreH128(smh + 6144, t, bv);
    CPC();
    for (int i = 0; i < KT; ++i) {
        if (i + 1 < KT) tloadH128(Qp, QLN, n0, (i + 1) * 16, t, bv);
        CPW0();
        __syncthreads();
        if (i + 1 < KT) {
            int s = (i + 1) & 1;
            cfillH(su + s * 6144, A, DD, m0, (i + 1) * 16, t);
            tstoreH128(smh + 6144 + s * 3072, t, bv);
            CPC();
        }
        mma_chunkH44(smh + (i & 1) * 3072, smh + 6144 + (i & 1) * 3072, acc, wm, wn, g, tg);
    }
    const float* bp = g_bias + b * CLN + m0;
    __half* Sp = g_Sh + (size_t)b * CLN * QLN;
    float cw[4][4][4];
#pragma unroll
    for (int mi = 0; mi < 4; ++mi)
#pragma unroll
        for (int h = 0; h < 2; ++h) {
            int row = m0 + wm + (mi << 4) + g + (h << 3);
            float bbv = bp[wm + (mi << 4) + g + (h << 3)];
#pragma unroll
            for (int ni = 0; ni < 4; ++ni) {
                float e0 = __expf(acc[mi][ni][2 * h] + bbv);
                float e1 = __expf(acc[mi][ni][2 * h + 1] + bbv);
                __half2 hp = __floats2half2_rn(e0, e1);
                int col = n0 + wn + (ni << 3) + (tg << 1);
                *(__half2*)(Sp + (size_t)row * QLN + col) = hp;
                cw[mi][ni][2 * h] = __low2float(hp);
                cw[mi][ni][2 * h + 1] = __high2float(hp);
            }
        }
    {
        float rs[4][2];
#pragma unroll
        for (int mi = 0; mi < 4; ++mi)
#pragma unroll
            for (int h = 0; h < 2; ++h) {
                float s = 0.f;
#pragma unroll
                for (int ni = 0; ni < 4; ++ni) s += cw[mi][ni][2 * h] + cw[mi][ni][2 * h + 1];
                rs[mi][h] = s;
            }
#pragma unroll
        for (int o = 1; o <= 2; o <<= 1)
#pragma unroll
            for (int mi = 0; mi < 4; ++mi)
#pragma unroll
                for (int h = 0; h < 2; ++h)
                    rs[mi][h] += __shfl_xor_sync(0xffffffffu, rs[mi][h], o);
        if (tg == 0) {
            float* rp = g_rsum + b * CLN + m0;
#pragma unroll
            for (int mi = 0; mi < 4; ++mi)
#pragma unroll
                for (int h = 0; h < 2; ++h)
                    atomicAdd(rp + wm + (mi << 4) + g + (h << 3), rs[mi][h]);
        }
    }
    {
        float cs[4][2];
#pragma unroll
        for (int ni = 0; ni < 4; ++ni)
#pragma unroll
            for (int p = 0; p < 2; ++p) {
                float s = 0.f;
#pragma unroll
                for (int mi = 0; mi < 4; ++mi) s += cw[mi][ni][p] + cw[mi][ni][2 + p];
                cs[ni][p] = s;
            }
#pragma unroll
        for (int o = 4; o <= 16; o <<= 1)
#pragma unroll
            for (int ni = 0; ni < 4; ++ni)
#pragma unroll
                for (int p = 0; p < 2; ++p)
                    cs[ni][p] += __shfl_xor_sync(0xffffffffu, cs[ni][p], o);
        if (g == 0) {
            float* cp = g_csum + b * QLN + n0;
#pragma unroll
            for (int ni = 0; ni < 4; ++ni)
#pragma unroll
                for (int p = 0; p < 2; ++p)
                    atomicAdd(cp + wn + (ni << 3) + (tg << 1) + p, cs[ni][p]);
        }
    }
}

// ---------------- G3: Tth[d][q] = (sum_c Ch[d][c] expSh[c][q]) / csum[q] ------
// M=128 (d), N=64 (q), K=1024 in 32 chunks of 32; 3-stage  (R13 config)
__global__ __launch_bounds__(256) void g3_mma() {
    __shared__ __align__(16) __half smh[23040];
    int b = blockIdx.y, n0 = blockIdx.x << 6;
    const __half* Ap = g_Ch + (size_t)b * DD * CLN;
    const __half* Ep = g_Sh + (size_t)b * CLN * QLN;
    uint32_t su = s2u(smh);
    int t = threadIdx.x, lane = t & 31, warp = t >> 5;
    int g = lane >> 2, tg = lane & 3;
    int wm = (warp >> 2) << 6, wn = (warp & 3) << 4;
    float acc[4][2][4] = {};
    const int KT = 32;
    __half bv[8];
    cfill32_128(su, Ap, CLN, 0, 0, t);
    CPC();
    tloadH64_32(Ep, QLN, n0, 0, t, bv);
    tstoreH64_32(smh + 15360, t, bv);
    tloadH64_32(Ep, QLN, n0, 32, t, bv);
    cfill32_128(su + 10240, Ap, CLN, 0, 32, t);
    CPC();
    for (int i = 0; i < KT; ++i) {
        if (i + 1 < KT) CPW1(); else CPW0();
        __syncthreads();
        if (i + 1 < KT) tstoreH64_32(smh + 15360 + ((i + 1) % 3) * 2560, t, bv);
        if (i + 2 < KT) {
            cfill32_128(su + ((i + 2) % 3) * 10240, Ap, CLN, 0, (i + 2) * 32, t);
            CPC();
            tloadH64_32(Ep, QLN, n0, (i + 2) * 32, t, bv);
        }
        mma_g3_k32(smh + (i % 3) * 5120, smh + 15360 + (i % 3) * 2560, acc, wm, wn, g, tg);
    }
    __half* Ttp = g_Tth + (size_t)b * DD * QLN;
    const float* ci = g_csum + b * QLN + n0;
    float r0[2], r1[2];
#pragma unroll
    for (int ni = 0; ni < 2; ++ni) {
        int col = wn + (ni << 3) + (tg << 1);
        r0[ni] = 1.f / ci[col];
        r1[ni] = 1.f / ci[col + 1];
    }
#pragma unroll
    for (int mi = 0; mi < 4; ++mi)
#pragma unroll
        for (int h = 0; h < 2; ++h) {
            int d = wm + (mi << 4) + g + (h << 3);
#pragma unroll
            for (int ni = 0; ni < 2; ++ni) {
                int col = wn + (ni << 3) + (tg << 1);
                *(__half2*)(Ttp + (size_t)d * QLN + n0 + col) =
                    __floats2half2_rn(acc[mi][ni][2 * h] * r0[ni],
                                      acc[mi][ni][2 * h + 1] * r1[ni]);
            }
        }
}

// ---------------- G24 fused: all four output blocks ---------------------------
// M=64 (c), N=128 (d), K=512 in 16 chunks of 32; R13 3-stage schedule,
// low-reg serialized helper, launch_bounds(256,3) for 3 CTA/SM occupancy test
// smem halves: A s*2560 [0,7680), B1 7680+s*5120 [7680,23040), B2 23040+s*5120
__global__ __launch_bounds__(256, 3) void g24_mma(const float* __restrict__ Cin,
                                                  float* __restrict__ out) {
    extern __shared__ __half smh[];
    int b = blockIdx.y, m0 = blockIdx.x << 6;
    const __half* A = g_Sh + (size_t)b * CLN * QLN;
    const __half* B1 = g_Qh + (size_t)b * DD * QLN;
    const __half* B2 = g_Tth + (size_t)b * DD * QLN;
    uint32_t su = s2u(smh);
    int t = threadIdx.x, lane = t & 31, warp = t >> 5;
    int g = lane >> 2, tg = lane & 3;
    int wm = (warp >> 2) << 5, wn = (warp & 3) << 5;
    float ac1[2][4][4] = {}, ac2[2][4][4] = {};
    const int KT = 16;
    cfill32_64(su, A, QLN, m0, 0, t);
    cfill32_128(su + 15360, B1, QLN, 0, 0, t);
    cfill32_128(su + 46080, B2, QLN, 0, 0, t);
    CPC();
    cfill32_64(su + 5120, A, QLN, m0, 32, t);
    cfill32_128(su + 15360 + 10240, B1, QLN, 0, 32, t);
    cfill32_128(su + 46080 + 10240, B2, QLN, 0, 32, t);
    CPC();
    for (int i = 0; i < KT; ++i) {
        if (i + 1 < KT) CPW1(); else CPW0();
        __syncthreads();
        if (i + 2 < KT) {
            int s = (i + 2) % 3;
            cfill32_64(su + s * 5120, A, QLN, m0, (i + 2) * 32, t);
            cfill32_128(su + 15360 + s * 10240, B1, QLN, 0, (i + 2) * 32, t);
            cfill32_128(su + 46080 + s * 10240, B2, QLN, 0, (i + 2) * 32, t);
            CPC();
        }
        int s = i % 3;
        mma_g24_k32(smh + s * 2560, smh + 7680 + s * 5120, smh + 23040 + s * 5120,
                    ac1, ac2, wm, wn, g, tg);
    }
    // epilogue: stage both outputs per 32-row chunk, write 4 output blocks
    const float* rp = g_rsum + b * CLN;
    size_t ob = (size_t)b * (4 * DD) * CLN;
    float* smf = (float*)smh;
    float* smX = smf;            // 32 x 133
    float* smY = smf + 4256;     // 32 x 133
    for (int ch = 0; ch < 2; ++ch) {
        __syncthreads();
        if ((warp >> 2) == ch) {
#pragma unroll
            for (int mi = 0; mi < 2; ++mi)
#pragma unroll
                for (int h = 0; h < 2; ++h) {
                    int ml = (mi << 4) + g + (h << 3);
                    int row = m0 + wm + (mi << 4) + g + (h << 3);
                    float sc = 1.f / rp[row];
#pragma unroll
                    for (int ni = 0; ni < 4; ++ni) {
                        int n = wn + (ni << 3) + (tg << 1);
                        smX[ml * 133 + n] = ac1[mi][ni][2 * h] * sc;
                        smX[ml * 133 + n + 1] = ac1[mi][ni][2 * h + 1] * sc;
                        smY[ml * 133 + n] = ac2[mi][ni][2 * h] * sc;
                        smY[ml * 133 + n + 1] = ac2[mi][ni][2 * h + 1] * sc;
                    }
                }
        }
        __syncthreads();
        int cl = t & 31, dw = t >> 5;
        int c = m0 + (ch << 5) + cl;
#pragma unroll
        for (int i = 0; i < 16; ++i) {
            int d = dw + (i << 3);
            float v1 = smX[cl * 133 + d];
            float v2 = smY[cl * 133 + d];
            float cv = Cin[((size_t)b * DD + d) * CLN + c];
            out[ob + (size_t)d * CLN + c] = cv;
            out[ob + (size_t)(DD + d) * CLN + c] = v1;
            out[ob + (size_t)(2 * DD + d) * CLN + c] = cv * v1;
            out[ob + (size_t)(3 * DD + d) * CLN + c] = cv * v2;
        }
    }
}

// ---------------- launch ------------------------------------------------------
extern "C" void kernel_launch(void* const* d_in, const int* in_sizes, int n_in,
                              void* d_out, int out_size) {
    const float* C = (const float*)d_in[0];
    const float* Q = (const float*)d_in[1];
    const float* W = (const float*)d_in[2];
    float* out = (float*)d_out;

    const int SM24 = 76800;  // 38400 halves (3-stage)
    cudaFuncSetAttribute(g24_mma, cudaFuncAttributeMaxDynamicSharedMemorySize, SM24);

    prepC_kernel<<<dim3(CLN / 64, BB), 256>>>(C, Q, W);
    g1_mma<<<dim3(QLN / 128, CLN / 128, BB), 256>>>();
    g3_mma<<<dim3(QLN / 64, BB), 256>>>();
    g24_mma<<<dim3(CLN / 64, BB), 256, SM24>>>(C, out);
}

// round 16
// speedup vs baseline: 1.5830x; 1.5830x over previous
#include <cuda_runtime.h>
#include <cuda_fp16.h>
#include <cstdint>

#define BB  32
#define DD  128
#define CLN 1024
#define QLN 512

// ---------------- scratch (device globals; no allocations allowed) ----------
__device__ __half g_Aeffh[BB * CLN * DD];          // wq + wqc*C^T (fp16)
__device__ float  g_bias[BB * CLN];
__device__ __half g_Sh[(size_t)BB * CLN * QLN];    // exp(S) fp16 (B, CL, QL)
__device__ float  g_rsum[BB * CLN];
__device__ float  g_csum[BB * QLN];
__device__ __half g_Tth[BB * DD * QLN];            // (S2^T C)^T fp16 (B, D, QL)
__device__ __half g_Qh[BB * DD * QLN];             // Q fp16
__device__ __half g_Ch[BB * DD * CLN];             // C fp16

// ---------------- helpers -----------------------------------------------------
__device__ __forceinline__ uint32_t s2u(const void* p) {
    uint32_t a;
    asm("{ .reg .u64 t; cvta.to.shared.u64 t, %1; cvt.u32.u64 %0, t; }" : "=r"(a) : "l"(p));
    return a;
}
#define CPC()  asm volatile("cp.async.commit_group;" ::: "memory")
#define CPW0() asm volatile("cp.async.wait_group 0;" ::: "memory")
#define CPW1() asm volatile("cp.async.wait_group 1;" ::: "memory")

// ---- K=16 rows (stride 24 halves = 48B), used by g1 --------------------------
__device__ __forceinline__ void cfillH(uint32_t sb, const __half* __restrict__ g,
                                       int ld, int row0, int k0, int t) {
    int r = t >> 1, q = t & 1;
    asm volatile("cp.async.cg.shared.global [%0], [%1], 16;"
                 :: "r"(sb + r * 48 + (q << 4)),
                    "l"(g + (size_t)(row0 + r) * ld + k0 + (q << 3)));
}
__device__ __forceinline__ void tloadH128(const __half* __restrict__ g, int ld,
                                          int n0, int k0, int t, __half v[8]) {
    int q = t & 127, cs = (t >> 7) << 3;
#pragma unroll
    for (int i = 0; i < 8; ++i)
        v[i] = g[(size_t)(k0 + cs + i) * ld + n0 + q];
}
__device__ __forceinline__ void tstoreH128(__half* __restrict__ smf, int t, const __half v[8]) {
    int q = t & 127, cs = (t >> 7) << 3;
#pragma unroll
    for (int j = 0; j < 4; ++j)
        *(__half2*)(smf + q * 24 + cs + 2 * j) = __halves2half2(v[2 * j], v[2 * j + 1]);
}

// ---- K=32 rows (stride 40 halves = 80B), used by g3/g24 ----------------------
__device__ __forceinline__ void cfill32_128(uint32_t sb, const __half* __restrict__ g,
                                            int ld, int row0, int k0, int t) {
#pragma unroll
    for (int j = 0; j < 2; ++j) {
        int lin = t + (j << 8);
        int r = lin >> 2, q = lin & 3;
        asm volatile("cp.async.cg.shared.global [%0], [%1], 16;"
                     :: "r"(sb + r * 80 + (q << 4)),
                        "l"(g + (size_t)(row0 + r) * ld + k0 + (q << 3)));
    }
}
__device__ __forceinline__ void cfill32_64(uint32_t sb, const __half* __restrict__ g,
                                           int ld, int row0, int k0, int t) {
    int r = t >> 2, q = t & 3;
    asm volatile("cp.async.cg.shared.global [%0], [%1], 16;"
                 :: "r"(sb + r * 80 + (q << 4)),
                    "l"(g + (size_t)(row0 + r) * ld + k0 + (q << 3)));
}
// transposed fill, 64-n x 32-k: each thread 8 k at fixed n  (g3 B)
__device__ __forceinline__ void tloadH64_32(const __half* __restrict__ g, int ld,
                                            int n0, int k0, int t, __half v[8]) {
    int q = t & 63, cs = (t >> 6) << 3;
#pragma unroll
    for (int i = 0; i < 8; ++i)
        v[i] = g[(size_t)(k0 + cs + i) * ld + n0 + q];
}
__device__ __forceinline__ void tstoreH64_32(__half* __restrict__ smf, int t, const __half v[8]) {
    int q = t & 63, cs = (t >> 6) << 3;
#pragma unroll
    for (int j = 0; j < 4; ++j)
        *(__half2*)(smf + q * 40 + cs + 2 * j) = __halves2half2(v[2 * j], v[2 * j + 1]);
}

// ---------------- mma.sync fp16 m16n8k16, fp32 accumulate ---------------------
#define MMA_F16(D, A, B)                                                           \
    asm volatile(                                                                  \
        "mma.sync.aligned.m16n8k16.row.col.f32.f16.f16.f32 "                       \
        "{%0,%1,%2,%3}, {%4,%5,%6,%7}, {%8,%9}, {%0,%1,%2,%3};"                    \
        : "+f"((D)[0]), "+f"((D)[1]), "+f"((D)[2]), "+f"((D)[3])                   \
        : "r"((A)[0]), "r"((A)[1]), "r"((A)[2]), "r"((A)[3]),                      \
          "r"((B)[0]), "r"((B)[1]))

// g1: warp tile 64x32 (4 mi x 4 ni), stride-24 smem, one k16
__device__ __forceinline__ void mma_chunkH44(const __half* __restrict__ As,
                                             const __half* __restrict__ Bs,
                                             float acc[4][4][4],
                                             int wm, int wn, int g, int tg) {
    int co = tg << 1;
    unsigned a[4][4], bf[4][2];
#pragma unroll
    for (int mi = 0; mi < 4; ++mi) {
        const __half* p = As + (wm + (mi << 4) + g) * 24 + co;
        a[mi][0] = *(const unsigned*)(p);
        a[mi][1] = *(const unsigned*)(p + 192);
        a[mi][2] = *(const unsigned*)(p + 8);
        a[mi][3] = *(const unsigned*)(p + 200);
    }
#pragma unroll
    for (int ni = 0; ni < 4; ++ni) {
        const __half* p = Bs + (wn + (ni << 3) + g) * 24 + co;
        bf[ni][0] = *(const unsigned*)(p);
        bf[ni][1] = *(const unsigned*)(p + 8);
    }
#pragma unroll
    for (int mi = 0; mi < 4; ++mi)
#pragma unroll
        for (int ni = 0; ni < 4; ++ni) MMA_F16(acc[mi][ni], a[mi], bf[ni]);
}

// g3: warp tile 64x16 (4 mi x 2 ni), stride-40 smem, K=32 (2 k16 steps)
__device__ __forceinline__ void mma_g3_k32(const __half* __restrict__ As,
                                           const __half* __restrict__ Bs,
                                           float acc[4][2][4],
                                           int wm, int wn, int g, int tg) {
#pragma unroll
    for (int k16 = 0; k16 < 2; ++k16) {
        int co = (k16 << 4) + (tg << 1);
        unsigned a[4][4], bf[2][2];
#pragma unroll
        for (int mi = 0; mi < 4; ++mi) {
            const __half* p = As + (wm + (mi << 4) + g) * 40 + co;
            a[mi][0] = *(const unsigned*)(p);
            a[mi][1] = *(const unsigned*)(p + 320);
            a[mi][2] = *(const unsigned*)(p + 8);
            a[mi][3] = *(const unsigned*)(p + 328);
        }
#pragma unroll
        for (int ni = 0; ni < 2; ++ni) {
            const __half* p = Bs + (wn + (ni << 3) + g) * 40 + co;
            bf[ni][0] = *(const unsigned*)(p);
            bf[ni][1] = *(const unsigned*)(p + 8);
        }
#pragma unroll
        for (int mi = 0; mi < 4; ++mi)
#pragma unroll
            for (int ni = 0; ni < 2; ++ni) MMA_F16(acc[mi][ni], a[mi], bf[ni]);
    }
}

// g24: warp tile 32x32 per B (2 mi x 4 ni), two B share A, stride-40, K=32
// (R13 version: all fragments loaded up front — do NOT serialize, do NOT cap regs)
__device__ __forceinline__ void mma_g24_k32(const __half* __restrict__ As,
                                            const __half* __restrict__ Bs1,
                                            const __half* __restrict__ Bs2,
                                            float ac1[2][4][4], float ac2[2][4][4],
                                            int wm, int wn, int g, int tg) {
#pragma unroll
    for (int k16 = 0; k16 < 2; ++k16) {
        int co = (k16 << 4) + (tg << 1);
        unsigned a[2][4], b1[4][2], b2[4][2];
#pragma unroll
        for (int mi = 0; mi < 2; ++mi) {
            const __half* p = As + (wm + (mi << 4) + g) * 40 + co;
            a[mi][0] = *(const unsigned*)(p);
            a[mi][1] = *(const unsigned*)(p + 320);
            a[mi][2] = *(const unsigned*)(p + 8);
            a[mi][3] = *(const unsigned*)(p + 328);
        }
#pragma unroll
        for (int ni = 0; ni < 4; ++ni) {
            const __half* p = Bs1 + (wn + (ni << 3) + g) * 40 + co;
            b1[ni][0] = *(const unsigned*)(p);
            b1[ni][1] = *(const unsigned*)(p + 8);
            const __half* p2 = Bs2 + (wn + (ni << 3) + g) * 40 + co;
            b2[ni][0] = *(const unsigned*)(p2);
            b2[ni][1] = *(const unsigned*)(p2 + 8);
        }
#pragma unroll
        for (int mi = 0; mi < 2; ++mi)
#pragma unroll
            for (int ni = 0; ni < 4; ++ni) {
                MMA_F16(ac1[mi][ni], a[mi], b1[ni]);
                MMA_F16(ac2[mi][ni], a[mi], b2[ni]);
            }
    }
}

// ---------------- prepC: Aeff/bias + fp16 copies of C and Q + zero sums -------
__global__ __launch_bounds__(256) void prepC_kernel(const float* __restrict__ C,
                                                    const float* __restrict__ Q,
                                                    const float* __restrict__ W) {
    __shared__ float tile[128 * 68];
    int b = blockIdx.y, c0 = blockIdx.x << 6, bx = blockIdx.x;
    int t = threadIdx.x, warp = t >> 5, lane = t & 31;
    int gi = (blockIdx.y * 16 + blockIdx.x) * 256 + t;
    if (gi < BB * CLN) g_rsum[gi] = 0.f;
    if (gi < BB * QLN) g_csum[gi] = 0.f;
#pragma unroll
    for (int i = 0; i < 8; ++i) {
        int idx = t + (i << 8);
        int d = idx >> 4, c4 = idx & 15;
        float4 v = *(const float4*)(C + ((size_t)b * DD + d) * CLN + c0 + (c4 << 2));
        *(float4*)(tile + d * 68 + (c4 << 2)) = v;
    }
    __syncthreads();
    // C -> fp16 copy (vectorized: 4 elems/thread/iter)
#pragma unroll
    for (int i = 0; i < 8; ++i) {
        int idx = t + (i << 8);
        int d = idx >> 4, cc = (idx & 15) << 2;
        const float* tp = tile + d * 68 + cc;
        __half* op = g_Ch + ((size_t)b * DD + d) * CLN + c0 + cc;
        *(__half2*)op = __floats2half2_rn(tp[0], tp[1]);
        *(__half2*)(op + 2) = __floats2half2_rn(tp[2], tp[3]);
    }
    // Q -> fp16 copy (vectorized float4)
    {
        const float* Qb = Q + (size_t)b * DD * QLN;
        __half* Qhb = g_Qh + (size_t)b * DD * QLN;
#pragma unroll
        for (int i = 0; i < 4; ++i) {
            int idx4 = bx * 1024 + i * 256 + t;
            float4 v = *(const float4*)(Qb + idx4 * 4);
            *(__half2*)(Qhb + idx4 * 4) = __floats2half2_rn(v.x, v.y);
            *(__half2*)(Qhb + idx4 * 4 + 2) = __floats2half2_rn(v.z, v.w);
        }
    }
#pragma unroll
    for (int k = 0; k < 8; ++k) {
        int cc = (warp << 3) + k;
        size_t rc = (size_t)b * CLN + c0 + cc;
        const float* w = W + rc * (3 * DD);
        int d0 = lane << 2;
        float4 wq = *(const float4*)(w + d0);
        float4 wc = *(const float4*)(w + DD + d0);
        float4 wqc = *(const float4*)(w + 2 * DD + d0);
        float ct0 = tile[(d0 + 0) * 68 + cc];
        float ct1 = tile[(d0 + 1) * 68 + cc];
        float ct2 = tile[(d0 + 2) * 68 + cc];
        float ct3 = tile[(d0 + 3) * 68 + cc];
        *(__half2*)(g_Aeffh + (rc << 7) + d0) =
            __floats2half2_rn(wq.x + wqc.x * ct0, wq.y + wqc.y * ct1);
        *(__half2*)(g_Aeffh + (rc << 7) + d0 + 2) =
            __floats2half2_rn(wq.z + wqc.z * ct2, wq.w + wqc.w * ct3);
        float v = wc.x * ct0 + wc.y * ct1 + wc.z * ct2 + wc.w * ct3;
#pragma unroll
        for (int o = 16; o; o >>= 1) v += __shfl_xor_sync(0xffffffffu, v, o);
        if (lane == 0) g_bias[rc] = v;
    }
}

// ---------------- G1: expSh = exp(Aeff @ Q + bias); row/col sums via atomics --
__global__ __launch_bounds__(256) void g1_mma() {
    __shared__ __align__(16) __half smh[12288];
    int b = blockIdx.z, n0 = blockIdx.x << 7, m0 = blockIdx.y << 7;
    const __half* A = g_Aeffh + (size_t)b * CLN * DD;
    const __half* Qp = g_Qh + (size_t)b * DD * QLN;
    uint32_t su = s2u(smh);
    int t = threadIdx.x, lane = t & 31, warp = t >> 5;
    int g = lane >> 2, tg = lane & 3;
    int wm = (warp >> 2) << 6, wn = (warp & 3) << 5;
    float acc[4][4][4] = {};
    const int KT = 8;
    __half bv[8];
    cfillH(su, A, DD, m0, 0, t);
    tloadH128(Qp, QLN, n0, 0, t, bv);
    tstoreH128(smh + 6144, t, bv);
    CPC();
    for (int i = 0; i < KT; ++i) {
        if (i + 1 < KT) tloadH128(Qp, QLN, n0, (i + 1) * 16, t, bv);
        CPW0();
        __syncthreads();
        if (i + 1 < KT) {
            int s = (i + 1) & 1;
            cfillH(su + s * 6144, A, DD, m0, (i + 1) * 16, t);
            tstoreH128(smh + 6144 + s * 3072, t, bv);
            CPC();
        }
        mma_chunkH44(smh + (i & 1) * 3072, smh + 6144 + (i & 1) * 3072, acc, wm, wn, g, tg);
    }
    const float* bp = g_bias + b * CLN + m0;
    __half* Sp = g_Sh + (size_t)b * CLN * QLN;
    float cw[4][4][4];
#pragma unroll
    for (int mi = 0; mi < 4; ++mi)
#pragma unroll
        for (int h = 0; h < 2; ++h) {
            int row = m0 + wm + (mi << 4) + g + (h << 3);
            float bbv = bp[wm + (mi << 4) + g + (h << 3)];
#pragma unroll
            for (int ni = 0; ni < 4; ++ni) {
                float e0 = __expf(acc[mi][ni][2 * h] + bbv);
                float e1 = __expf(acc[mi][ni][2 * h + 1] + bbv);
                __half2 hp = __floats2half2_rn(e0, e1);
                int col = n0 + wn + (ni << 3) + (tg << 1);
                *(__half2*)(Sp + (size_t)row * QLN + col) = hp;
                cw[mi][ni][2 * h] = __low2float(hp);
                cw[mi][ni][2 * h + 1] = __high2float(hp);
            }
        }
    {
        float rs[4][2];
#pragma unroll
        for (int mi = 0; mi < 4; ++mi)
#pragma unroll
            for (int h = 0; h < 2; ++h) {
                float s = 0.f;
#pragma unroll
                for (int ni = 0; ni < 4; ++ni) s += cw[mi][ni][2 * h] + cw[mi][ni][2 * h + 1];
                rs[mi][h] = s;
            }
#pragma unroll
        for (int o = 1; o <= 2; o <<= 1)
#pragma unroll
            for (int mi = 0; mi < 4; ++mi)
#pragma unroll
                for (int h = 0; h < 2; ++h)
                    rs[mi][h] += __shfl_xor_sync(0xffffffffu, rs[mi][h], o);
        if (tg == 0) {
            float* rp = g_rsum + b * CLN + m0;
#pragma unroll
            for (int mi = 0; mi < 4; ++mi)
#pragma unroll
                for (int h = 0; h < 2; ++h)
                    atomicAdd(rp + wm + (mi << 4) + g + (h << 3), rs[mi][h]);
        }
    }
    {
        float cs[4][2];
#pragma unroll
        for (int ni = 0; ni < 4; ++ni)
#pragma unroll
            for (int p = 0; p < 2; ++p) {
                float s = 0.f;
#pragma unroll
                for (int mi = 0; mi < 4; ++mi) s += cw[mi][ni][p] + cw[mi][ni][2 + p];
                cs[ni][p] = s;
            }
#pragma unroll
        for (int o = 4; o <= 16; o <<= 1)
#pragma unroll
            for (int ni = 0; ni < 4; ++ni)
#pragma unroll
                for (int p = 0; p < 2; ++p)
                    cs[ni][p] += __shfl_xor_sync(0xffffffffu, cs[ni][p], o);
        if (g == 0) {
            float* cp = g_csum + b * QLN + n0;
#pragma unroll
            for (int ni = 0; ni < 4; ++ni)
#pragma unroll
                for (int p = 0; p < 2; ++p)
                    atomicAdd(cp + wn + (ni << 3) + (tg << 1) + p, cs[ni][p]);
        }
    }
}

// ---------------- G3: Tth[d][q] = (sum_c Ch[d][c] expSh[c][q]) / csum[q] ------
// M=128 (d), N=64 (q), K=1024 in 32 chunks of 32; 3-stage  (R13 config)
__global__ __launch_bounds__(256) void g3_mma() {
    __shared__ __align__(16) __half smh[23040];
    int b = blockIdx.y, n0 = blockIdx.x << 6;
    const __half* Ap = g_Ch + (size_t)b * DD * CLN;
    const __half* Ep = g_Sh + (size_t)b * CLN * QLN;
    uint32_t su = s2u(smh);
    int t = threadIdx.x, lane = t & 31, warp = t >> 5;
    int g = lane >> 2, tg = lane & 3;
    int wm = (warp >> 2) << 6, wn = (warp & 3) << 4;
    float acc[4][2][4] = {};
    const int KT = 32;
    __half bv[8];
    cfill32_128(su, Ap, CLN, 0, 0, t);
    CPC();
    tloadH64_32(Ep, QLN, n0, 0, t, bv);
    tstoreH64_32(smh + 15360, t, bv);
    tloadH64_32(Ep, QLN, n0, 32, t, bv);
    cfill32_128(su + 10240, Ap, CLN, 0, 32, t);
    CPC();
    for (int i = 0; i < KT; ++i) {
        if (i + 1 < KT) CPW1(); else CPW0();
        __syncthreads();
        if (i + 1 < KT) tstoreH64_32(smh + 15360 + ((i + 1) % 3) * 2560, t, bv);
        if (i + 2 < KT) {
            cfill32_128(su + ((i + 2) % 3) * 10240, Ap, CLN, 0, (i + 2) * 32, t);
            CPC();
            tloadH64_32(Ep, QLN, n0, (i + 2) * 32, t, bv);
        }
        mma_g3_k32(smh + (i % 3) * 5120, smh + 15360 + (i % 3) * 2560, acc, wm, wn, g, tg);
    }
    __half* Ttp = g_Tth + (size_t)b * DD * QLN;
    const float* ci = g_csum + b * QLN + n0;
    float r0[2], r1[2];
#pragma unroll
    for (int ni = 0; ni < 2; ++ni) {
        int col = wn + (ni << 3) + (tg << 1);
        r0[ni] = 1.f / ci[col];
        r1[ni] = 1.f / ci[col + 1];
    }
#pragma unroll
    for (int mi = 0; mi < 4; ++mi)
#pragma unroll
        for (int h = 0; h < 2; ++h) {
            int d = wm + (mi << 4) + g + (h << 3);
#pragma unroll
            for (int ni = 0; ni < 2; ++ni) {
                int col = wn + (ni << 3) + (tg << 1);
                *(__half2*)(Ttp + (size_t)d * QLN + n0 + col) =
                    __floats2half2_rn(acc[mi][ni][2 * h] * r0[ni],
                                      acc[mi][ni][2 * h + 1] * r1[ni]);
            }
        }
}

// ---------------- G24 fused: all four output blocks ---------------------------
// M=64 (c), N=128 (d), K=512 in 16 chunks of 32; 3-stage (R13 config, no reg cap)
// smem halves: A s*2560 [0,7680), B1 7680+s*5120 [7680,23040), B2 23040+s*5120
__global__ __launch_bounds__(256) void g24_mma(const float* __restrict__ Cin,
                                               float* __restrict__ out) {
    extern __shared__ __half smh[];
    int b = blockIdx.y, m0 = blockIdx.x << 6;
    const __half* A = g_Sh + (size_t)b * CLN * QLN;
    const __half* B1 = g_Qh + (size_t)b * DD * QLN;
    const __half* B2 = g_Tth + (size_t)b * DD * QLN;
    uint32_t su = s2u(smh);
    int t = threadIdx.x, lane = t & 31, warp = t >> 5;
    int g = lane >> 2, tg = lane & 3;
    int wm = (warp >> 2) << 5, wn = (warp & 3) << 5;
    float ac1[2][4][4] = {}, ac2[2][4][4] = {};
    const int KT = 16;
    cfill32_64(su, A, QLN, m0, 0, t);
    cfill32_128(su + 15360, B1, QLN, 0, 0, t);
    cfill32_128(su + 46080, B2, QLN, 0, 0, t);
    CPC();
    cfill32_64(su + 5120, A, QLN, m0, 32, t);
    cfill32_128(su + 15360 + 10240, B1, QLN, 0, 32, t);
    cfill32_128(su + 46080 + 10240, B2, QLN, 0, 32, t);
    CPC();
    for (int i = 0; i < KT; ++i) {
        if (i + 1 < KT) CPW1(); else CPW0();
        __syncthreads();
        if (i + 2 < KT) {
            int s = (i + 2) % 3;
            cfill32_64(su + s * 5120, A, QLN, m0, (i + 2) * 32, t);
            cfill32_128(su + 15360 + s * 10240, B1, QLN, 0, (i + 2) * 32, t);
            cfill32_128(su + 46080 + s * 10240, B2, QLN, 0, (i + 2) * 32, t);
            CPC();
        }
        int s = i % 3;
        mma_g24_k32(smh + s * 2560, smh + 7680 + s * 5120, smh + 23040 + s * 5120,
                    ac1, ac2, wm, wn, g, tg);
    }
    // epilogue: stage both outputs per 32-row chunk, write 4 output blocks
    const float* rp = g_rsum + b * CLN;
    size_t ob = (size_t)b * (4 * DD) * CLN;
    float* smf = (float*)smh;
    float* smX = smf;            // 32 x 133
    float* smY = smf + 4256;     // 32 x 133
    for (int ch = 0; ch < 2; ++ch) {
        __syncthreads();
        if ((warp >> 2) == ch) {
#pragma unroll
            for (int mi = 0; mi < 2; ++mi)
#pragma unroll
                for (int h = 0; h < 2; ++h) {
                    int ml = (mi << 4) + g + (h << 3);
                    int row = m0 + wm + (mi << 4) + g + (h << 3);
                    float sc = 1.f / rp[row];
#pragma unroll
                    for (int ni = 0; ni < 4; ++ni) {
                        int n = wn + (ni << 3) + (tg << 1);
                        smX[ml * 133 + n] = ac1[mi][ni][2 * h] * sc;
                        smX[ml * 133 + n + 1] = ac1[mi][ni][2 * h + 1] * sc;
                        smY[ml * 133 + n] = ac2[mi][ni][2 * h] * sc;
                        smY[ml * 133 + n + 1] = ac2[mi][ni][2 * h + 1] * sc;
                    }
                }
        }
        __syncthreads();
        int cl = t & 31, dw = t >> 5;
        int c = m0 + (ch << 5) + cl;
#pragma unroll
        for (int i = 0; i < 16; ++i) {
            int d = dw + (i << 3);
            float v1 = smX[cl * 133 + d];
            float v2 = smY[cl * 133 + d];
            float cv = Cin[((size_t)b * DD + d) * CLN + c];
            out[ob + (size_t)d * CLN + c] = cv;
            out[ob + (size_t)(DD + d) * CLN + c] = v1;
            out[ob + (size_t)(2 * DD + d) * CLN + c] = cv * v1;
            out[ob + (size_t)(3 * DD + d) * CLN + c] = cv * v2;
        }
    }
}

// ---------------- launch ------------------------------------------------------
extern "C" void kernel_launch(void* const* d_in, const int* in_sizes, int n_in,
                              void* d_out, int out_size) {
    const float* C = (const float*)d_in[0];
    const float* Q = (const float*)d_in[1];
    const float* W = (const float*)d_in[2];
    float* out = (float*)d_out;

    const int SM24 = 76800;  // 38400 halves (3-stage)
    cudaFuncSetAttribute(g24_mma, cudaFuncAttributeMaxDynamicSharedMemorySize, SM24);

    prepC_kernel<<<dim3(CLN / 64, BB), 256>>>(C, Q, W);
    g1_mma<<<dim3(QLN / 128, CLN / 128, BB), 256>>>();
    g3_mma<<<dim3(QLN / 64, BB), 256>>>();
    g24_mma<<<dim3(CLN / 64, BB), 256, SM24>>>(C, out);
}